// round 11
// baseline (speedup 1.0000x reference)
#include <cuda_runtime.h>
#include <cstdint>

#define CONST_N 25000
#define CONST_E 300000
#define CONST_G 256
#define DIM0 92
#define DIM1 256

// ---------------- scratch (device globals; no allocation allowed) ----------
__device__ __align__(16) float g_x0[CONST_N * DIM0 + 16];
__device__ __align__(16) float g_x [CONST_N * DIM1 + 16];
__device__ __align__(16) float g_agg[CONST_N * DIM1 + 16];
__device__ __align__(16) float g_gsum[CONST_G * DIM1];
__device__ __align__(16) float g_gcnt[CONST_G];

// ---------------- helpers --------------------------------------------------
__device__ __forceinline__ float softplus_f(float z) {
    return (z > 20.f) ? z : __logf(1.f + __expf(z));
}
__device__ __forceinline__ unsigned long long pack2(float lo, float hi) {
    unsigned long long r;
    asm("mov.b64 %0, {%1,%2};" : "=l"(r) : "f"(lo), "f"(hi));
    return r;
}
__device__ __forceinline__ float2 unpack2(unsigned long long v) {
    float2 r;
    asm("mov.b64 {%0,%1}, %2;" : "=f"(r.x), "=f"(r.y) : "l"(v));
    return r;
}
// packed dual-FMA (sm_100+): 2 fp32 FMAs per instruction
__device__ __forceinline__ void ffma2(unsigned long long& d, unsigned long long a,
                                      unsigned long long b) {
    asm("fma.rn.f32x2 %0, %1, %2, %0;" : "+l"(d) : "l"(a), "l"(b));
}
// no-return vector atomic add (sm_90+)
__device__ __forceinline__ void red_add_f4(float* p, float4 v) {
    asm volatile("red.global.add.v4.f32 [%0], {%1,%2,%3,%4};"
                 :: "l"(p), "f"(v.x), "f"(v.y), "f"(v.z), "f"(v.w) : "memory");
}

// ---------------- embedding gather ----------------------------------------
__global__ void embedA_kernel(const int* __restrict__ atoms,
                              const float* __restrict__ emb) {
    int i = blockIdx.x * blockDim.x + threadIdx.x;
    if (i >= CONST_N * DIM0) return;
    int n = i / DIM0;
    int c = i - n * DIM0;
    g_x0[i] = emb[atoms[n] * DIM0 + c];
}

// ---------------- zero kernels ---------------------------------------------
__global__ void zeroA_agg_kernel(int n4) {
    float4 z = make_float4(0.f, 0.f, 0.f, 0.f);
    for (int i = blockIdx.x * blockDim.x + threadIdx.x; i < n4;
         i += gridDim.x * blockDim.x)
        ((float4*)g_agg)[i] = z;
}
__global__ void zeroA_pool_kernel() {
    int i = blockIdx.x * blockDim.x + threadIdx.x;
    if (i < CONST_G * DIM1) g_gsum[i] = 0.f;
    if (i < CONST_G) g_gcnt[i] = 0.f;
}

// ---------------- fused edge conv ------------------------------------------
// ee = softplus(ea @ w1 + b1) @ w2 + b2   (A computed on the fly, never stored)
// msg = ee * x[src];  agg[dst] += msg     (fused epilogue, vector RED atomics)
// Identical math/loads to the validated R1 kernel; the ONLY change is that the
// next B chunk is prefetched into registers while the current chunk computes.
template<int C, int BN>
__global__ __launch_bounds__(256)
void edgeA_conv_kernel(const float* __restrict__ ea,
                       const int* __restrict__ srcg,
                       const int* __restrict__ dstg,
                       const float* __restrict__ w1,   // [4, C]
                       const float* __restrict__ b1,   // [C]
                       const float* __restrict__ w2,   // [C, C]
                       const float* __restrict__ b2)   // [C]
{
    constexpr int BM = 64;
    constexpr int BK = 16;
    constexpr int KT = (C + BK - 1) / BK;
    constexpr int NC = BN / 32;            // cols per thread (8 for 256, 4 for 128)
    constexpr int NB4 = BK * BN / 4 / 256; // float4 B loads per thread (4 / 2)

    const float* x = (C == DIM0) ? g_x0 : g_x;
    float* agg = g_agg;

    __shared__ float ea_s[BM][4];
    __shared__ int   src_s[BM];
    __shared__ int   dst_s[BM];
    __shared__ float As[BK][BM];
    __shared__ float Bs[BK][BN];

    const int tid = threadIdx.x;
    const int tn  = tid & 31;
    const int ty  = tid >> 5;
    const int e0  = blockIdx.x * BM;

    if (tid < BM) {
        int e = e0 + tid;
        float4 v = make_float4(0.f, 0.f, 0.f, 0.f);
        int sv = 0, dv = 0;
        if (e < CONST_E) {
            v = *(const float4*)&ea[e * 4];
            sv = srcg[e];
            dv = dstg[e];
        }
        *(float4*)&ea_s[tid][0] = v;
        src_s[tid] = sv;
        dst_s[tid] = dv;
    }

    unsigned long long acc2[4][NC];
#pragma unroll
    for (int p = 0; p < 4; p++)
#pragma unroll
        for (int j = 0; j < NC; j++) acc2[p][j] = 0ull;

    // conflict-free column mapping: octet of threads spans 32 distinct banks
    const int cnA = (BN == 256) ? ((tn >> 3) * 64 + (tn & 7) * 4) : (tn * 4);
    // A-compute mapping: thread -> As[ak][am..am+3]
    const int ak = tid >> 4;
    const int am = (tid & 15) * 4;

    // prefetch B chunk 0 into registers (guards identical to R1's loader)
    float4 bpre[NB4];
#pragma unroll
    for (int j = 0; j < NB4; j++) {
        int ls = tid + j * 256;
        int k = ls / (BN / 4);
        int n = (ls % (BN / 4)) * 4;
        float4 v = make_float4(0.f, 0.f, 0.f, 0.f);
        if (k < C && n < C) v = *(const float4*)&w2[k * C + n];
        bpre[j] = v;
    }

    for (int kt = 0; kt < KT; kt++) {
        const int k0 = kt * BK;
        __syncthreads();
        // commit prefetched B chunk to shared
#pragma unroll
        for (int j = 0; j < NB4; j++) {
            int ls = tid + j * 256;
            int k = ls / (BN / 4);
            int n = (ls % (BN / 4)) * 4;
            *(float4*)&Bs[k][n] = bpre[j];
        }
        // compute As = softplus(ea @ w1 + b1) chunk on the fly (same as R1)
        {
            int kg = k0 + ak;
            float4 av = make_float4(0.f, 0.f, 0.f, 0.f);
            if (kg < C) {
                float w10 = w1[0 * C + kg];
                float w11 = w1[1 * C + kg];
                float w12 = w1[2 * C + kg];
                float w13 = w1[3 * C + kg];
                float b1v = b1[kg];
                float* o = &av.x;
#pragma unroll
                for (int jj = 0; jj < 4; jj++) {
                    float4 e4 = *(float4*)&ea_s[am + jj][0];
                    float z = b1v + e4.x * w10 + e4.y * w11 + e4.z * w12 + e4.w * w13;
                    o[jj] = softplus_f(z);
                }
            }
            *(float4*)&As[ak][am] = av;
        }
        __syncthreads();
        // prefetch NEXT B chunk (overlaps with the compute below)
        if (kt + 1 < KT) {
            const int k0n = (kt + 1) * BK;
#pragma unroll
            for (int j = 0; j < NB4; j++) {
                int ls = tid + j * 256;
                int k = ls / (BN / 4);
                int n = (ls % (BN / 4)) * 4;
                float4 v = make_float4(0.f, 0.f, 0.f, 0.f);
                int kg = k0n + k;
                if (kg < C && n < C) v = *(const float4*)&w2[kg * C + n];
                bpre[j] = v;
            }
        }
#pragma unroll
        for (int k = 0; k < BK; k++) {
            const unsigned long long* a64 =
                (const unsigned long long*)&As[k][ty * 8];
            unsigned long long a2[4] = {a64[0], a64[1], a64[2], a64[3]};
            unsigned long long bb[8];
            float4 bA = *(const float4*)&Bs[k][cnA];
            bb[0] = pack2(bA.x, bA.x);
            bb[1] = pack2(bA.y, bA.y);
            bb[2] = pack2(bA.z, bA.z);
            bb[3] = pack2(bA.w, bA.w);
            if constexpr (BN == 256) {
                float4 bB = *(const float4*)&Bs[k][cnA + 32];
                bb[4] = pack2(bB.x, bB.x);
                bb[5] = pack2(bB.y, bB.y);
                bb[6] = pack2(bB.z, bB.z);
                bb[7] = pack2(bB.w, bB.w);
            }
#pragma unroll
            for (int p = 0; p < 4; p++)
#pragma unroll
                for (int j = 0; j < NC; j++) ffma2(acc2[p][j], a2[p], bb[j]);
        }
    }

    // epilogue: bias, gather x[src], multiply, scatter-add to agg[dst]
    float4 biasA = make_float4(0.f, 0.f, 0.f, 0.f);
    float4 biasB = make_float4(0.f, 0.f, 0.f, 0.f);
    if (cnA < C) biasA = *(const float4*)&b2[cnA];
    if constexpr (BN == 256) {
        if (cnA + 32 < C) biasB = *(const float4*)&b2[cnA + 32];
    }

#pragma unroll
    for (int i = 0; i < 8; i++) {
        int m = ty * 8 + i;
        int e = e0 + m;
        if (e >= CONST_E) continue;
        int sv = src_s[m];
        int dv = dst_s[m];
        if (cnA < C) {
            float4 xv = *(const float4*)&x[(size_t)sv * C + cnA];
            float2 f0 = unpack2(acc2[i >> 1][0]);
            float2 f1 = unpack2(acc2[i >> 1][1]);
            float2 f2 = unpack2(acc2[i >> 1][2]);
            float2 f3 = unpack2(acc2[i >> 1][3]);
            float a0 = (i & 1) ? f0.y : f0.x;
            float a1 = (i & 1) ? f1.y : f1.x;
            float a2v = (i & 1) ? f2.y : f2.x;
            float a3 = (i & 1) ? f3.y : f3.x;
            float4 o;
            o.x = (a0 + biasA.x) * xv.x;
            o.y = (a1 + biasA.y) * xv.y;
            o.z = (a2v + biasA.z) * xv.z;
            o.w = (a3 + biasA.w) * xv.w;
            red_add_f4(&agg[(size_t)dv * C + cnA], o);
        }
        if constexpr (BN == 256) {
            int cnB = cnA + 32;
            if (cnB < C) {
                float4 xv = *(const float4*)&x[(size_t)sv * C + cnB];
                float2 f4 = unpack2(acc2[i >> 1][4]);
                float2 f5 = unpack2(acc2[i >> 1][5]);
                float2 f6 = unpack2(acc2[i >> 1][6]);
                float2 f7 = unpack2(acc2[i >> 1][7]);
                float a4 = (i & 1) ? f4.y : f4.x;
                float a5 = (i & 1) ? f5.y : f5.x;
                float a6 = (i & 1) ? f6.y : f6.x;
                float a7 = (i & 1) ? f7.y : f7.x;
                float4 o;
                o.x = (a4 + biasB.x) * xv.x;
                o.y = (a5 + biasB.y) * xv.y;
                o.z = (a6 + biasB.z) * xv.z;
                o.w = (a7 + biasB.w) * xv.w;
                red_add_f4(&agg[(size_t)dv * C + cnB], o);
            }
        }
    }
}

// ---------------- node linear: x = softplus(agg @ w + b) -------------------
// Same math/guards as R1; next chunk's A and B prefetched into registers.
template<int CIN>
__global__ __launch_bounds__(256)
void nodeA_gemm_kernel(const float* __restrict__ w,   // [CIN, 256]
                       const float* __restrict__ b)   // [256]
{
    constexpr int BM = 64, BK = 16, BN = 256;
    constexpr int KT = (CIN + BK - 1) / BK;
    const float* A = g_agg;   // [N, CIN]
    float* out = g_x;         // [N, 256]

    __shared__ float As[BK][BM];
    __shared__ float Bs[BK][BN];

    const int tid = threadIdx.x;
    const int tn  = tid & 31;
    const int ty  = tid >> 5;
    const int n0  = blockIdx.x * BM;

    unsigned long long acc2[4][8];
#pragma unroll
    for (int p = 0; p < 4; p++)
#pragma unroll
        for (int j = 0; j < 8; j++) acc2[p][j] = 0ull;

    const int cnA = (tn >> 3) * 64 + (tn & 7) * 4;
    const int lm = tid & 63;
    const int lk = (tid >> 6) * 4;
    const int arow = n0 + lm;

    // prefetch chunk 0 (B: guarded like R1; A: guarded like R1 incl. tail)
    float4 bpre[4], apre;
#pragma unroll
    for (int j = 0; j < 4; j++) {
        int ls = tid + j * 256;
        int k = ls >> 6;
        int n = (ls & 63) * 4;
        float4 v = make_float4(0.f, 0.f, 0.f, 0.f);
        if (k < CIN) v = *(const float4*)&w[k * BN + n];
        bpre[j] = v;
    }
    {
        apre = make_float4(0.f, 0.f, 0.f, 0.f);
        if (arow < CONST_N) {
            if (lk + 3 < CIN) {
                apre = *(const float4*)&A[(size_t)arow * CIN + lk];
            } else {
                float* o = &apre.x;
#pragma unroll
                for (int j = 0; j < 4; j++)
                    o[j] = (lk + j < CIN) ? A[(size_t)arow * CIN + lk + j] : 0.f;
            }
        }
    }

    for (int kt = 0; kt < KT; kt++) {
        __syncthreads();
#pragma unroll
        for (int j = 0; j < 4; j++) {
            int ls = tid + j * 256;
            int k = ls >> 6;
            int n = (ls & 63) * 4;
            *(float4*)&Bs[k][n] = bpre[j];
        }
        As[lk + 0][lm] = apre.x;
        As[lk + 1][lm] = apre.y;
        As[lk + 2][lm] = apre.z;
        As[lk + 3][lm] = apre.w;
        __syncthreads();
        if (kt + 1 < KT) {
            const int k0n = (kt + 1) * BK;
#pragma unroll
            for (int j = 0; j < 4; j++) {
                int ls = tid + j * 256;
                int k = ls >> 6;
                int n = (ls & 63) * 4;
                float4 v = make_float4(0.f, 0.f, 0.f, 0.f);
                int kg = k0n + k;
                if (kg < CIN) v = *(const float4*)&w[kg * BN + n];
                bpre[j] = v;
            }
            apre = make_float4(0.f, 0.f, 0.f, 0.f);
            int kg = k0n + lk;
            if (arow < CONST_N) {
                if (kg + 3 < CIN) {
                    apre = *(const float4*)&A[(size_t)arow * CIN + kg];
                } else {
                    float* o = &apre.x;
#pragma unroll
                    for (int j = 0; j < 4; j++)
                        o[j] = (kg + j < CIN) ? A[(size_t)arow * CIN + kg + j] : 0.f;
                }
            }
        }
#pragma unroll
        for (int k = 0; k < BK; k++) {
            const unsigned long long* a64 =
                (const unsigned long long*)&As[k][ty * 8];
            unsigned long long a2[4] = {a64[0], a64[1], a64[2], a64[3]};
            unsigned long long bb[8];
            float4 bA = *(const float4*)&Bs[k][cnA];
            float4 bB = *(const float4*)&Bs[k][cnA + 32];
            bb[0] = pack2(bA.x, bA.x);
            bb[1] = pack2(bA.y, bA.y);
            bb[2] = pack2(bA.z, bA.z);
            bb[3] = pack2(bA.w, bA.w);
            bb[4] = pack2(bB.x, bB.x);
            bb[5] = pack2(bB.y, bB.y);
            bb[6] = pack2(bB.z, bB.z);
            bb[7] = pack2(bB.w, bB.w);
#pragma unroll
            for (int p = 0; p < 4; p++)
#pragma unroll
                for (int j = 0; j < 8; j++) ffma2(acc2[p][j], a2[p], bb[j]);
        }
    }

    float4 biasA = *(const float4*)&b[cnA];
    float4 biasB = *(const float4*)&b[cnA + 32];
#pragma unroll
    for (int i = 0; i < 8; i++) {
        int row = n0 + ty * 8 + i;
        if (row >= CONST_N) continue;
        {
            float2 f0 = unpack2(acc2[i >> 1][0]);
            float2 f1 = unpack2(acc2[i >> 1][1]);
            float2 f2 = unpack2(acc2[i >> 1][2]);
            float2 f3 = unpack2(acc2[i >> 1][3]);
            float4 o;
            o.x = softplus_f(((i & 1) ? f0.y : f0.x) + biasA.x);
            o.y = softplus_f(((i & 1) ? f1.y : f1.x) + biasA.y);
            o.z = softplus_f(((i & 1) ? f2.y : f2.x) + biasA.z);
            o.w = softplus_f(((i & 1) ? f3.y : f3.x) + biasA.w);
            *(float4*)&out[(size_t)row * 256 + cnA] = o;
        }
        {
            float2 f4 = unpack2(acc2[i >> 1][4]);
            float2 f5 = unpack2(acc2[i >> 1][5]);
            float2 f6 = unpack2(acc2[i >> 1][6]);
            float2 f7 = unpack2(acc2[i >> 1][7]);
            float4 o;
            o.x = softplus_f(((i & 1) ? f4.y : f4.x) + biasB.x);
            o.y = softplus_f(((i & 1) ? f5.y : f5.x) + biasB.y);
            o.z = softplus_f(((i & 1) ? f6.y : f6.x) + biasB.z);
            o.w = softplus_f(((i & 1) ? f7.y : f7.x) + biasB.w);
            *(float4*)&out[(size_t)row * 256 + cnA + 32] = o;
        }
    }
}

// ---------------- global mean pool (atomics; batch is L2-hot) --------------
__global__ void poolA_kernel(const int* __restrict__ batch) {
    int i = blockIdx.x * blockDim.x + threadIdx.x;
    if (i >= CONST_N * 64) return;
    int n = i >> 6;
    int c4 = i & 63;
    int bg = batch[n];
    float4 v = *(const float4*)&g_x[(size_t)n * 256 + c4 * 4];
    red_add_f4(&g_gsum[bg * 256 + c4 * 4], v);
    if (c4 == 0) atomicAdd(&g_gcnt[bg], 1.f);
}

// ---------------- readout MLP (one block per graph) ------------------------
__global__ __launch_bounds__(256)
void readoutA_kernel(const float* __restrict__ rw1, const float* __restrict__ rb1,
                     const float* __restrict__ rw2, const float* __restrict__ rb2,
                     const float* __restrict__ rw3, const float* __restrict__ rb3,
                     float* __restrict__ out) {
    __shared__ float gs[256];
    __shared__ float h1s[256];
    __shared__ float h2s[128];
    __shared__ float red_s[8];
    int g = blockIdx.x;
    int c = threadIdx.x;
    float cnt = fmaxf(g_gcnt[g], 1.f);
    gs[c] = g_gsum[g * 256 + c] / cnt;
    __syncthreads();
    float z = rb1[c];
#pragma unroll 8
    for (int k = 0; k < 256; k++) z += gs[k] * rw1[k * 256 + c];
    h1s[c] = softplus_f(z);
    __syncthreads();
    if (c < 128) {
        float z2 = rb2[c];
#pragma unroll 8
        for (int k = 0; k < 256; k++) z2 += h1s[k] * rw2[k * 128 + c];
        h2s[c] = softplus_f(z2);
    }
    __syncthreads();
    float p = (c < 128) ? h2s[c] * rw3[c] : 0.f;
#pragma unroll
    for (int off = 16; off; off >>= 1) p += __shfl_down_sync(0xffffffffu, p, off);
    if ((c & 31) == 0) red_s[c >> 5] = p;
    __syncthreads();
    if (c == 0) {
        float t = 0.f;
#pragma unroll
        for (int i = 0; i < 8; i++) t += red_s[i];
        out[g] = t + rb3[0];
    }
}

// ---------------- launch ----------------------------------------------------
extern "C" void kernel_launch(void* const* d_in, const int* in_sizes, int n_in,
                              void* d_out, int out_size) {
    (void)in_sizes; (void)n_in; (void)out_size;
    const int*   x_atoms = (const int*)d_in[0];
    const int*   ei      = (const int*)d_in[1];
    const float* ea      = (const float*)d_in[2];
    const int*   batch   = (const int*)d_in[3];
    const float* emb     = (const float*)d_in[4];
    const float* ew1_0   = (const float*)d_in[5];
    const float* eb1_0   = (const float*)d_in[6];
    const float* ew2_0   = (const float*)d_in[7];
    const float* eb2_0   = (const float*)d_in[8];
    const float* nw_0    = (const float*)d_in[9];
    const float* nb_0    = (const float*)d_in[10];
    const float* ew1     = (const float*)d_in[11];
    const float* eb1     = (const float*)d_in[12];
    const float* ew2     = (const float*)d_in[13];
    const float* eb2     = (const float*)d_in[14];
    const float* nw      = (const float*)d_in[15];
    const float* nb      = (const float*)d_in[16];
    const float* rw1     = (const float*)d_in[17];
    const float* rb1     = (const float*)d_in[18];
    const float* rw2     = (const float*)d_in[19];
    const float* rb2     = (const float*)d_in[20];
    const float* rw3     = (const float*)d_in[21];
    const float* rb3     = (const float*)d_in[22];
    float* out = (float*)d_out;

    const int* srcg = ei;
    const int* dstg = ei + CONST_E;

    const int EB = (CONST_E + 63) / 64;   // 4688
    const int NB = (CONST_N + 63) / 64;   // 391

    embedA_kernel<<<(CONST_N * DIM0 + 255) / 256, 256>>>(x_atoms, emb);

    // layer 0 (92-dim, original unpadded weights, guarded loads)
    zeroA_agg_kernel<<<1024, 256>>>(CONST_N * DIM0 / 4);
    edgeA_conv_kernel<DIM0, 128><<<EB, 256>>>(ea, srcg, dstg,
                                              ew1_0, eb1_0, ew2_0, eb2_0);
    nodeA_gemm_kernel<DIM0><<<NB, 256>>>(nw_0, nb_0);

    // layers 1..3 (256-dim)
    for (int i = 0; i < 3; i++) {
        zeroA_agg_kernel<<<2048, 256>>>(CONST_N * DIM1 / 4);
        edgeA_conv_kernel<DIM1, 256><<<EB, 256>>>(
            ea, srcg, dstg,
            ew1 + i * 4 * DIM1, eb1 + i * DIM1,
            ew2 + i * DIM1 * DIM1, eb2 + i * DIM1);
        nodeA_gemm_kernel<DIM1><<<NB, 256>>>(nw + i * DIM1 * DIM1, nb + i * DIM1);
    }

    // pooling + readout
    zeroA_pool_kernel<<<(CONST_G * DIM1 + 255) / 256, 256>>>();
    poolA_kernel<<<(CONST_N * 64 + 255) / 256, 256>>>(batch);
    readoutA_kernel<<<CONST_G, 256>>>(rw1, rb1, rw2, rb2, rw3, rb3, out);
}

// round 12
// speedup vs baseline: 1.0293x; 1.0293x over previous
#include <cuda_runtime.h>
#include <cstdint>

#define CONST_N 25000
#define CONST_E 300000
#define CONST_G 256
#define DIM0 92
#define DIM1 256

// ---------------- scratch (device globals; no allocation allowed) ----------
__device__ __align__(16) float g_x0[CONST_N * DIM0 + 16];
__device__ __align__(16) float g_x [CONST_N * DIM1 + 16];
__device__ __align__(16) float g_agg[CONST_N * DIM1 + 16];
__device__ __align__(16) float g_gsum[CONST_G * DIM1];
__device__ __align__(16) float g_gcnt[CONST_G];

// ---------------- helpers --------------------------------------------------
__device__ __forceinline__ float softplus_f(float z) {
    return (z > 20.f) ? z : __logf(1.f + __expf(z));
}
__device__ __forceinline__ unsigned long long pack2(float lo, float hi) {
    unsigned long long r;
    asm("mov.b64 %0, {%1,%2};" : "=l"(r) : "f"(lo), "f"(hi));
    return r;
}
__device__ __forceinline__ float2 unpack2(unsigned long long v) {
    float2 r;
    asm("mov.b64 {%0,%1}, %2;" : "=f"(r.x), "=f"(r.y) : "l"(v));
    return r;
}
// packed dual-FMA (sm_100+): 2 fp32 FMAs per instruction
__device__ __forceinline__ void ffma2(unsigned long long& d, unsigned long long a,
                                      unsigned long long b) {
    asm("fma.rn.f32x2 %0, %1, %2, %0;" : "+l"(d) : "l"(a), "l"(b));
}
// no-return vector atomic add (sm_90+)
__device__ __forceinline__ void red_add_f4(float* p, float4 v) {
    asm volatile("red.global.add.v4.f32 [%0], {%1,%2,%3,%4};"
                 :: "l"(p), "f"(v.x), "f"(v.y), "f"(v.z), "f"(v.w) : "memory");
}

// ---------------- embedding gather ----------------------------------------
__global__ void embedB_kernel(const int* __restrict__ atoms,
                              const float* __restrict__ emb) {
    int i = blockIdx.x * blockDim.x + threadIdx.x;
    if (i >= CONST_N * DIM0) return;
    int n = i / DIM0;
    int c = i - n * DIM0;
    g_x0[i] = emb[atoms[n] * DIM0 + c];
}

// ---------------- zero kernels ---------------------------------------------
__global__ void zeroB_agg_kernel(int n4) {
    float4 z = make_float4(0.f, 0.f, 0.f, 0.f);
    for (int i = blockIdx.x * blockDim.x + threadIdx.x; i < n4;
         i += gridDim.x * blockDim.x)
        ((float4*)g_agg)[i] = z;
}
__global__ void zeroB_pool_kernel() {
    int i = blockIdx.x * blockDim.x + threadIdx.x;
    if (i < CONST_G * DIM1) g_gsum[i] = 0.f;
    if (i < CONST_G) g_gcnt[i] = 0.f;
}

// ---------------- fused edge conv (N-split for occupancy) -------------------
// ee = softplus(ea @ w1 + b1) @ w2 + b2   (A computed on the fly, never stored)
// msg = ee * x[src];  agg[dst] += msg     (fused epilogue, vector RED atomics)
// BN=128 columns per CTA; blockIdx.y selects the 128-col half (colbase).
// Smaller accumulator file (acc2[4][4]) -> 3 CTAs/SM via launch_bounds(256,3).
template<int C>
__global__ __launch_bounds__(256, 3)
void edgeB_conv_kernel(const float* __restrict__ ea,
                       const int* __restrict__ srcg,
                       const int* __restrict__ dstg,
                       const float* __restrict__ w1,   // [4, C]
                       const float* __restrict__ b1,   // [C]
                       const float* __restrict__ w2,   // [C, C]
                       const float* __restrict__ b2)   // [C]
{
    constexpr int BM = 64;
    constexpr int BK = 16;
    constexpr int BN = 128;
    constexpr int KT = (C + BK - 1) / BK;

    const float* x = (C == DIM0) ? g_x0 : g_x;
    float* agg = g_agg;

    __shared__ float ea_s[BM][4];
    __shared__ int   src_s[BM];
    __shared__ int   dst_s[BM];
    __shared__ float As[BK][BM];
    __shared__ float Bs[BK][BN];

    const int tid = threadIdx.x;
    const int tn  = tid & 31;
    const int ty  = tid >> 5;
    const int e0  = blockIdx.x * BM;
    const int colbase = blockIdx.y * BN;

    if (tid < BM) {
        int e = e0 + tid;
        float4 v = make_float4(0.f, 0.f, 0.f, 0.f);
        int sv = 0, dv = 0;
        if (e < CONST_E) {
            v = *(const float4*)&ea[e * 4];
            sv = srcg[e];
            dv = dstg[e];
        }
        *(float4*)&ea_s[tid][0] = v;
        src_s[tid] = sv;
        dst_s[tid] = dv;
    }

    unsigned long long acc2[4][4];
#pragma unroll
    for (int p = 0; p < 4; p++)
#pragma unroll
        for (int j = 0; j < 4; j++) acc2[p][j] = 0ull;

    const int cnA = tn * 4;            // column within this half
    const int cnG = colbase + cnA;     // global column
    // A-compute mapping: thread -> As[ak][am..am+3]
    const int ak = tid >> 4;
    const int am = (tid & 15) * 4;

    for (int kt = 0; kt < KT; kt++) {
        const int k0 = kt * BK;
        __syncthreads();
        // load Bs = w2 chunk (columns [colbase, colbase+128))
#pragma unroll
        for (int ls = tid; ls < BK * BN / 4; ls += 256) {
            int k = ls / (BN / 4);
            int n = (ls % (BN / 4)) * 4;
            int kg = k0 + k;
            int ng = colbase + n;
            float4 v = make_float4(0.f, 0.f, 0.f, 0.f);
            if (kg < C && ng < C) v = *(const float4*)&w2[kg * C + ng];
            *(float4*)&Bs[k][n] = v;
        }
        // compute As = softplus(ea @ w1 + b1) chunk on the fly
        {
            int kg = k0 + ak;
            float4 av = make_float4(0.f, 0.f, 0.f, 0.f);
            if (kg < C) {
                float w10 = w1[0 * C + kg];
                float w11 = w1[1 * C + kg];
                float w12 = w1[2 * C + kg];
                float w13 = w1[3 * C + kg];
                float b1v = b1[kg];
                float* o = &av.x;
#pragma unroll
                for (int jj = 0; jj < 4; jj++) {
                    float4 e4 = *(float4*)&ea_s[am + jj][0];
                    float z = b1v + e4.x * w10 + e4.y * w11 + e4.z * w12 + e4.w * w13;
                    o[jj] = softplus_f(z);
                }
            }
            *(float4*)&As[ak][am] = av;
        }
        __syncthreads();
#pragma unroll
        for (int k = 0; k < BK; k++) {
            const unsigned long long* a64 =
                (const unsigned long long*)&As[k][ty * 8];
            unsigned long long a2[4] = {a64[0], a64[1], a64[2], a64[3]};
            unsigned long long bb[4];
            float4 bA = *(const float4*)&Bs[k][cnA];
            bb[0] = pack2(bA.x, bA.x);
            bb[1] = pack2(bA.y, bA.y);
            bb[2] = pack2(bA.z, bA.z);
            bb[3] = pack2(bA.w, bA.w);
#pragma unroll
            for (int p = 0; p < 4; p++)
#pragma unroll
                for (int j = 0; j < 4; j++) ffma2(acc2[p][j], a2[p], bb[j]);
        }
    }

    // epilogue: bias, gather x[src], multiply, scatter-add to agg[dst]
    float4 biasA = make_float4(0.f, 0.f, 0.f, 0.f);
    if (cnG < C) biasA = *(const float4*)&b2[cnG];

#pragma unroll
    for (int i = 0; i < 8; i++) {
        int m = ty * 8 + i;
        int e = e0 + m;
        if (e >= CONST_E) continue;
        int sv = src_s[m];
        int dv = dst_s[m];
        if (cnG < C) {
            float4 xv = *(const float4*)&x[(size_t)sv * C + cnG];
            float2 f0 = unpack2(acc2[i >> 1][0]);
            float2 f1 = unpack2(acc2[i >> 1][1]);
            float2 f2 = unpack2(acc2[i >> 1][2]);
            float2 f3 = unpack2(acc2[i >> 1][3]);
            float a0 = (i & 1) ? f0.y : f0.x;
            float a1 = (i & 1) ? f1.y : f1.x;
            float a2v = (i & 1) ? f2.y : f2.x;
            float a3 = (i & 1) ? f3.y : f3.x;
            float4 o;
            o.x = (a0 + biasA.x) * xv.x;
            o.y = (a1 + biasA.y) * xv.y;
            o.z = (a2v + biasA.z) * xv.z;
            o.w = (a3 + biasA.w) * xv.w;
            red_add_f4(&agg[(size_t)dv * C + cnG], o);
        }
    }
}

// ---------------- node linear: x = softplus(agg @ w + b) (R1-exact) --------
template<int CIN>
__global__ __launch_bounds__(256)
void nodeB_gemm_kernel(const float* __restrict__ w,   // [CIN, 256]
                       const float* __restrict__ b)   // [256]
{
    constexpr int BM = 64, BK = 16, BN = 256;
    constexpr int KT = (CIN + BK - 1) / BK;
    const float* A = g_agg;   // [N, CIN]
    float* out = g_x;         // [N, 256]

    __shared__ float As[BK][BM];
    __shared__ float Bs[BK][BN];

    const int tid = threadIdx.x;
    const int tn  = tid & 31;
    const int ty  = tid >> 5;
    const int n0  = blockIdx.x * BM;

    unsigned long long acc2[4][8];
#pragma unroll
    for (int p = 0; p < 4; p++)
#pragma unroll
        for (int j = 0; j < 8; j++) acc2[p][j] = 0ull;

    const int cnA = (tn >> 3) * 64 + (tn & 7) * 4;
    const int lm = tid & 63;
    const int lk = (tid >> 6) * 4;

    for (int kt = 0; kt < KT; kt++) {
        const int k0 = kt * BK;
        __syncthreads();
#pragma unroll
        for (int ls = tid; ls < BK * BN / 4; ls += 256) {
            int k = ls >> 6;
            int n = (ls & 63) * 4;
            int kg = k0 + k;
            float4 v = make_float4(0.f, 0.f, 0.f, 0.f);
            if (kg < CIN) v = *(const float4*)&w[kg * BN + n];
            *(float4*)&Bs[k][n] = v;
        }
        {
            int row = n0 + lm;
            int kg = k0 + lk;
            float4 v = make_float4(0.f, 0.f, 0.f, 0.f);
            if (row < CONST_N) {
                if (kg + 3 < CIN) {
                    v = *(const float4*)&A[(size_t)row * CIN + kg];
                } else {
                    float* o = &v.x;
#pragma unroll
                    for (int j = 0; j < 4; j++)
                        o[j] = (kg + j < CIN) ? A[(size_t)row * CIN + kg + j] : 0.f;
                }
            }
            As[lk + 0][lm] = v.x;
            As[lk + 1][lm] = v.y;
            As[lk + 2][lm] = v.z;
            As[lk + 3][lm] = v.w;
        }
        __syncthreads();
#pragma unroll
        for (int k = 0; k < BK; k++) {
            const unsigned long long* a64 =
                (const unsigned long long*)&As[k][ty * 8];
            unsigned long long a2[4] = {a64[0], a64[1], a64[2], a64[3]};
            unsigned long long bb[8];
            float4 bA = *(const float4*)&Bs[k][cnA];
            float4 bB = *(const float4*)&Bs[k][cnA + 32];
            bb[0] = pack2(bA.x, bA.x);
            bb[1] = pack2(bA.y, bA.y);
            bb[2] = pack2(bA.z, bA.z);
            bb[3] = pack2(bA.w, bA.w);
            bb[4] = pack2(bB.x, bB.x);
            bb[5] = pack2(bB.y, bB.y);
            bb[6] = pack2(bB.z, bB.z);
            bb[7] = pack2(bB.w, bB.w);
#pragma unroll
            for (int p = 0; p < 4; p++)
#pragma unroll
                for (int j = 0; j < 8; j++) ffma2(acc2[p][j], a2[p], bb[j]);
        }
    }

    float4 biasA = *(const float4*)&b[cnA];
    float4 biasB = *(const float4*)&b[cnA + 32];
#pragma unroll
    for (int i = 0; i < 8; i++) {
        int row = n0 + ty * 8 + i;
        if (row >= CONST_N) continue;
        {
            float2 f0 = unpack2(acc2[i >> 1][0]);
            float2 f1 = unpack2(acc2[i >> 1][1]);
            float2 f2 = unpack2(acc2[i >> 1][2]);
            float2 f3 = unpack2(acc2[i >> 1][3]);
            float4 o;
            o.x = softplus_f(((i & 1) ? f0.y : f0.x) + biasA.x);
            o.y = softplus_f(((i & 1) ? f1.y : f1.x) + biasA.y);
            o.z = softplus_f(((i & 1) ? f2.y : f2.x) + biasA.z);
            o.w = softplus_f(((i & 1) ? f3.y : f3.x) + biasA.w);
            *(float4*)&out[(size_t)row * 256 + cnA] = o;
        }
        {
            float2 f4 = unpack2(acc2[i >> 1][4]);
            float2 f5 = unpack2(acc2[i >> 1][5]);
            float2 f6 = unpack2(acc2[i >> 1][6]);
            float2 f7 = unpack2(acc2[i >> 1][7]);
            float4 o;
            o.x = softplus_f(((i & 1) ? f4.y : f4.x) + biasB.x);
            o.y = softplus_f(((i & 1) ? f5.y : f5.x) + biasB.y);
            o.z = softplus_f(((i & 1) ? f6.y : f6.x) + biasB.z);
            o.w = softplus_f(((i & 1) ? f7.y : f7.x) + biasB.w);
            *(float4*)&out[(size_t)row * 256 + cnA + 32] = o;
        }
    }
}

// ---------------- global mean pool (atomics; batch is L2-hot) --------------
__global__ void poolB_kernel(const int* __restrict__ batch) {
    int i = blockIdx.x * blockDim.x + threadIdx.x;
    if (i >= CONST_N * 64) return;
    int n = i >> 6;
    int c4 = i & 63;
    int bg = batch[n];
    float4 v = *(const float4*)&g_x[(size_t)n * 256 + c4 * 4];
    red_add_f4(&g_gsum[bg * 256 + c4 * 4], v);
    if (c4 == 0) atomicAdd(&g_gcnt[bg], 1.f);
}

// ---------------- readout MLP (one block per graph) ------------------------
__global__ __launch_bounds__(256)
void readoutB_kernel(const float* __restrict__ rw1, const float* __restrict__ rb1,
                     const float* __restrict__ rw2, const float* __restrict__ rb2,
                     const float* __restrict__ rw3, const float* __restrict__ rb3,
                     float* __restrict__ out) {
    __shared__ float gs[256];
    __shared__ float h1s[256];
    __shared__ float h2s[128];
    __shared__ float red_s[8];
    int g = blockIdx.x;
    int c = threadIdx.x;
    float cnt = fmaxf(g_gcnt[g], 1.f);
    gs[c] = g_gsum[g * 256 + c] / cnt;
    __syncthreads();
    float z = rb1[c];
#pragma unroll 8
    for (int k = 0; k < 256; k++) z += gs[k] * rw1[k * 256 + c];
    h1s[c] = softplus_f(z);
    __syncthreads();
    if (c < 128) {
        float z2 = rb2[c];
#pragma unroll 8
        for (int k = 0; k < 256; k++) z2 += h1s[k] * rw2[k * 128 + c];
        h2s[c] = softplus_f(z2);
    }
    __syncthreads();
    float p = (c < 128) ? h2s[c] * rw3[c] : 0.f;
#pragma unroll
    for (int off = 16; off; off >>= 1) p += __shfl_down_sync(0xffffffffu, p, off);
    if ((c & 31) == 0) red_s[c >> 5] = p;
    __syncthreads();
    if (c == 0) {
        float t = 0.f;
#pragma unroll
        for (int i = 0; i < 8; i++) t += red_s[i];
        out[g] = t + rb3[0];
    }
}

// ---------------- launch ----------------------------------------------------
extern "C" void kernel_launch(void* const* d_in, const int* in_sizes, int n_in,
                              void* d_out, int out_size) {
    (void)in_sizes; (void)n_in; (void)out_size;
    const int*   x_atoms = (const int*)d_in[0];
    const int*   ei      = (const int*)d_in[1];
    const float* ea      = (const float*)d_in[2];
    const int*   batch   = (const int*)d_in[3];
    const float* emb     = (const float*)d_in[4];
    const float* ew1_0   = (const float*)d_in[5];
    const float* eb1_0   = (const float*)d_in[6];
    const float* ew2_0   = (const float*)d_in[7];
    const float* eb2_0   = (const float*)d_in[8];
    const float* nw_0    = (const float*)d_in[9];
    const float* nb_0    = (const float*)d_in[10];
    const float* ew1     = (const float*)d_in[11];
    const float* eb1     = (const float*)d_in[12];
    const float* ew2     = (const float*)d_in[13];
    const float* eb2     = (const float*)d_in[14];
    const float* nw      = (const float*)d_in[15];
    const float* nb      = (const float*)d_in[16];
    const float* rw1     = (const float*)d_in[17];
    const float* rb1     = (const float*)d_in[18];
    const float* rw2     = (const float*)d_in[19];
    const float* rb2     = (const float*)d_in[20];
    const float* rw3     = (const float*)d_in[21];
    const float* rb3     = (const float*)d_in[22];
    float* out = (float*)d_out;

    const int* srcg = ei;
    const int* dstg = ei + CONST_E;

    const int EB = (CONST_E + 63) / 64;   // 4688
    const int NB = (CONST_N + 63) / 64;   // 391

    embedB_kernel<<<(CONST_N * DIM0 + 255) / 256, 256>>>(x_atoms, emb);

    // layer 0 (92-dim; single 128-col half covers all columns)
    zeroB_agg_kernel<<<1024, 256>>>(CONST_N * DIM0 / 4);
    edgeB_conv_kernel<DIM0><<<dim3(EB, 1), 256>>>(ea, srcg, dstg,
                                                  ew1_0, eb1_0, ew2_0, eb2_0);
    nodeB_gemm_kernel<DIM0><<<NB, 256>>>(nw_0, nb_0);

    // layers 1..3 (256-dim; two 128-col halves via grid.y for occupancy)
    for (int i = 0; i < 3; i++) {
        zeroB_agg_kernel<<<2048, 256>>>(CONST_N * DIM1 / 4);
        edgeB_conv_kernel<DIM1><<<dim3(EB, 2), 256>>>(
            ea, srcg, dstg,
            ew1 + i * 4 * DIM1, eb1 + i * DIM1,
            ew2 + i * DIM1 * DIM1, eb2 + i * DIM1);
        nodeB_gemm_kernel<DIM1><<<NB, 256>>>(nw + i * DIM1 * DIM1, nb + i * DIM1);
    }

    // pooling + readout
    zeroB_pool_kernel<<<(CONST_G * DIM1 + 255) / 256, 256>>>();
    poolB_kernel<<<(CONST_N * 64 + 255) / 256, 256>>>(batch);
    readoutB_kernel<<<CONST_G, 256>>>(rw1, rb1, rw2, rb2, rw3, rb3, out);
}

// round 17
// speedup vs baseline: 1.3008x; 1.2638x over previous
#include <cuda_runtime.h>
#include <cstdint>

#define CONST_N 25000
#define CONST_E 300000
#define CONST_G 256
#define DIM0 92
#define DIM1 256

// ---------------- scratch (device globals; no allocation allowed) ----------
__device__ __align__(16) float g_x0[CONST_N * DIM0 + 16];
__device__ __align__(16) float g_x [CONST_N * DIM1 + 16];
__device__ __align__(16) float g_agg[CONST_N * DIM1 + 16];
__device__ __align__(16) float g_gsum[CONST_G * DIM1];
__device__ __align__(16) float g_gcnt[CONST_G];

// ---------------- helpers --------------------------------------------------
__device__ __forceinline__ float softplus_f(float z) {
    return (z > 20.f) ? z : __logf(1.f + __expf(z));
}
__device__ __forceinline__ unsigned long long pack2(float lo, float hi) {
    unsigned long long r;
    asm("mov.b64 %0, {%1,%2};" : "=l"(r) : "f"(lo), "f"(hi));
    return r;
}
__device__ __forceinline__ float2 unpack2(unsigned long long v) {
    float2 r;
    asm("mov.b64 {%0,%1}, %2;" : "=f"(r.x), "=f"(r.y) : "l"(v));
    return r;
}
// packed dual-FMA (sm_100+): 2 fp32 FMAs per instruction
__device__ __forceinline__ void ffma2(unsigned long long& d, unsigned long long a,
                                      unsigned long long b) {
    asm("fma.rn.f32x2 %0, %1, %2, %0;" : "+l"(d) : "l"(a), "l"(b));
}
// no-return vector atomic add (sm_90+)
__device__ __forceinline__ void red_add_f4(float* p, float4 v) {
    asm volatile("red.global.add.v4.f32 [%0], {%1,%2,%3,%4};"
                 :: "l"(p), "f"(v.x), "f"(v.y), "f"(v.z), "f"(v.w) : "memory");
}
// cp.async 16B with zero-fill via src-size (0 or 16)
__device__ __forceinline__ void cp16(uint32_t dst_smem, const float* src, int sz) {
    size_t gp = __cvta_generic_to_global(src);
    asm volatile("cp.async.cg.shared.global [%0], [%1], 16, %2;"
                 :: "r"(dst_smem), "l"(gp), "r"(sz) : "memory");
}
__device__ __forceinline__ void cp_commit() {
    asm volatile("cp.async.commit_group;" ::: "memory");
}
__device__ __forceinline__ void cp_wait1() {
    asm volatile("cp.async.wait_group 1;" ::: "memory");
}
__device__ __forceinline__ void cp_wait0() {
    asm volatile("cp.async.wait_group 0;" ::: "memory");
}

// ---------------- embedding gather ----------------------------------------
__global__ void embedC_kernel(const int* __restrict__ atoms,
                              const float* __restrict__ emb) {
    int i = blockIdx.x * blockDim.x + threadIdx.x;
    if (i >= CONST_N * DIM0) return;
    int n = i / DIM0;
    int c = i - n * DIM0;
    g_x0[i] = emb[atoms[n] * DIM0 + c];
}

// ---------------- zero kernels ---------------------------------------------
__global__ void zeroC_agg_kernel(int n4) {
    float4 z = make_float4(0.f, 0.f, 0.f, 0.f);
    for (int i = blockIdx.x * blockDim.x + threadIdx.x; i < n4;
         i += gridDim.x * blockDim.x)
        ((float4*)g_agg)[i] = z;
}
__global__ void zeroC_pool_kernel() {
    int i = blockIdx.x * blockDim.x + threadIdx.x;
    if (i < CONST_G * DIM1) g_gsum[i] = 0.f;
    if (i < CONST_G) g_gcnt[i] = 0.f;
}

// ---------------- fused edge conv (cp.async double-buffered B) --------------
// ee = softplus(ea @ w1 + b1) @ w2 + b2   (A computed on the fly, never stored)
// msg = ee * x[src];  agg[dst] += msg     (fused epilogue, vector RED atomics)
// R1 geometry + inner loop; B chunks staged via cp.async one chunk ahead.
template<int C, int BN>
__global__ __launch_bounds__(256, 2)
void edgeC_conv_kernel(const float* __restrict__ ea,
                       const int* __restrict__ srcg,
                       const int* __restrict__ dstg,
                       const float* __restrict__ w1,   // [4, C]
                       const float* __restrict__ b1,   // [C]
                       const float* __restrict__ w2,   // [C, C]
                       const float* __restrict__ b2)   // [C]
{
    constexpr int BM = 64;
    constexpr int BK = 16;
    constexpr int KT = (C + BK - 1) / BK;
    constexpr int KPAD = KT * BK;
    constexpr int NC = BN / 32;            // cols per thread (8 / 4)
    constexpr int NB4 = BK * BN / 4 / 256; // float4 B loads per thread (4 / 2)
    constexpr bool FULL = (C % BK == 0) && (C >= BN);  // true for C=256

    const float* x = (C == DIM0) ? g_x0 : g_x;
    float* agg = g_agg;

    __shared__ float ea_s[BM][4];
    __shared__ int   src_s[BM];
    __shared__ int   dst_s[BM];
    __shared__ float w1s[4][KPAD];
    __shared__ float b1s[KPAD];
    __shared__ float As[BK][BM];
    __shared__ float Bs[2][BK][BN];

    const int tid = threadIdx.x;
    const int tn  = tid & 31;
    const int ty  = tid >> 5;
    const int e0  = blockIdx.x * BM;

    const uint32_t bs_base =
        (uint32_t)__cvta_generic_to_shared(&Bs[0][0][0]);

    if (tid < BM) {
        int e = e0 + tid;
        float4 v = make_float4(0.f, 0.f, 0.f, 0.f);
        int sv = 0, dv = 0;
        if (e < CONST_E) {
            v = *(const float4*)&ea[e * 4];
            sv = srcg[e];
            dv = dstg[e];
        }
        *(float4*)&ea_s[tid][0] = v;
        src_s[tid] = sv;
        dst_s[tid] = dv;
    }
    // hoist w1/b1 into smem (once)
    for (int i = tid; i < 4 * KPAD; i += 256) {
        int r = i / KPAD, c = i - r * KPAD;
        w1s[r][c] = (c < C) ? w1[r * C + c] : 0.f;
    }
    for (int i = tid; i < KPAD; i += 256)
        b1s[i] = (i < C) ? b1[i] : 0.f;

    // issue B chunk kt into stage s
    auto issueB = [&](int kt, int s) {
        const int k0 = kt * BK;
#pragma unroll
        for (int j = 0; j < NB4; j++) {
            int ls = tid + j * 256;
            int k = ls / (BN / 4);
            int n = (ls % (BN / 4)) * 4;
            int kg = k0 + k;
            uint32_t dst = bs_base + (uint32_t)(((s * BK + k) * BN + n) * 4);
            if (FULL) {
                cp16(dst, &w2[kg * C + n], 16);
            } else {
                int sz = (kg < C && n + 3 < C) ? 16 : 0;
                const float* src = sz ? &w2[kg * C + n] : w2;
                cp16(dst, src, sz);
            }
        }
        cp_commit();
    };

    unsigned long long acc2[4][NC];
#pragma unroll
    for (int p = 0; p < 4; p++)
#pragma unroll
        for (int j = 0; j < NC; j++) acc2[p][j] = 0ull;

    // conflict-free column mapping
    const int cnA = (BN == 256) ? ((tn >> 3) * 64 + (tn & 7) * 4) : (tn * 4);
    // A-compute mapping
    const int ak = tid >> 4;
    const int am = (tid & 15) * 4;

    issueB(0, 0);   // prologue

    for (int kt = 0; kt < KT; kt++) {
        const int s = kt & 1;
        const int k0 = kt * BK;
        __syncthreads();                          // (a)
        if (kt + 1 < KT) issueB(kt + 1, s ^ 1);
        // build As = softplus(ea @ w1 + b1) chunk (w1/b1 from smem)
        {
            int kg = k0 + ak;
            float4 av = make_float4(0.f, 0.f, 0.f, 0.f);
            if ((C % BK == 0) || (kg < C)) {
                float w10 = w1s[0][kg];
                float w11 = w1s[1][kg];
                float w12 = w1s[2][kg];
                float w13 = w1s[3][kg];
                float b1v = b1s[kg];
                float* o = &av.x;
#pragma unroll
                for (int jj = 0; jj < 4; jj++) {
                    float4 e4 = *(float4*)&ea_s[am + jj][0];
                    float z = b1v + e4.x * w10 + e4.y * w11 + e4.z * w12 + e4.w * w13;
                    o[jj] = softplus_f(z);
                }
            }
            *(float4*)&As[ak][am] = av;
        }
        if (kt + 1 < KT) cp_wait1(); else cp_wait0();
        __syncthreads();                          // (b)
#pragma unroll
        for (int k = 0; k < BK; k++) {
            const unsigned long long* a64 =
                (const unsigned long long*)&As[k][ty * 8];
            unsigned long long a2[4] = {a64[0], a64[1], a64[2], a64[3]};
            unsigned long long bb[8];
            float4 bA = *(const float4*)&Bs[s][k][cnA];
            bb[0] = pack2(bA.x, bA.x);
            bb[1] = pack2(bA.y, bA.y);
            bb[2] = pack2(bA.z, bA.z);
            bb[3] = pack2(bA.w, bA.w);
            if constexpr (BN == 256) {
                float4 bB = *(const float4*)&Bs[s][k][cnA + 32];
                bb[4] = pack2(bB.x, bB.x);
                bb[5] = pack2(bB.y, bB.y);
                bb[6] = pack2(bB.z, bB.z);
                bb[7] = pack2(bB.w, bB.w);
            }
#pragma unroll
            for (int p = 0; p < 4; p++)
#pragma unroll
                for (int j = 0; j < NC; j++) ffma2(acc2[p][j], a2[p], bb[j]);
        }
    }

    // epilogue: bias, gather x[src], multiply, scatter-add to agg[dst]
    float4 biasA = make_float4(0.f, 0.f, 0.f, 0.f);
    float4 biasB = make_float4(0.f, 0.f, 0.f, 0.f);
    if (cnA < C) biasA = *(const float4*)&b2[cnA];
    if constexpr (BN == 256) {
        if (cnA + 32 < C) biasB = *(const float4*)&b2[cnA + 32];
    }

#pragma unroll
    for (int i = 0; i < 8; i++) {
        int m = ty * 8 + i;
        int e = e0 + m;
        if (e >= CONST_E) continue;
        int sv = src_s[m];
        int dv = dst_s[m];
        if (cnA < C) {
            float4 xv = *(const float4*)&x[(size_t)sv * C + cnA];
            float2 f0 = unpack2(acc2[i >> 1][0]);
            float2 f1 = unpack2(acc2[i >> 1][1]);
            float2 f2 = unpack2(acc2[i >> 1][2]);
            float2 f3 = unpack2(acc2[i >> 1][3]);
            float a0 = (i & 1) ? f0.y : f0.x;
            float a1 = (i & 1) ? f1.y : f1.x;
            float a2v = (i & 1) ? f2.y : f2.x;
            float a3 = (i & 1) ? f3.y : f3.x;
            float4 o;
            o.x = (a0 + biasA.x) * xv.x;
            o.y = (a1 + biasA.y) * xv.y;
            o.z = (a2v + biasA.z) * xv.z;
            o.w = (a3 + biasA.w) * xv.w;
            red_add_f4(&agg[(size_t)dv * C + cnA], o);
        }
        if constexpr (BN == 256) {
            int cnB = cnA + 32;
            if (cnB < C) {
                float4 xv = *(const float4*)&x[(size_t)sv * C + cnB];
                float2 f4 = unpack2(acc2[i >> 1][4]);
                float2 f5 = unpack2(acc2[i >> 1][5]);
                float2 f6 = unpack2(acc2[i >> 1][6]);
                float2 f7 = unpack2(acc2[i >> 1][7]);
                float a4 = (i & 1) ? f4.y : f4.x;
                float a5 = (i & 1) ? f5.y : f5.x;
                float a6 = (i & 1) ? f6.y : f6.x;
                float a7 = (i & 1) ? f7.y : f7.x;
                float4 o;
                o.x = (a4 + biasB.x) * xv.x;
                o.y = (a5 + biasB.y) * xv.y;
                o.z = (a6 + biasB.z) * xv.z;
                o.w = (a7 + biasB.w) * xv.w;
                red_add_f4(&agg[(size_t)dv * C + cnB], o);
            }
        }
    }
}

// ---------------- node linear: x = softplus(agg @ w + b) -------------------
// R1 math; B via cp.async double buffer, A via 4-reg prefetch after barrier.
template<int CIN>
__global__ __launch_bounds__(256, 2)
void nodeC_gemm_kernel(const float* __restrict__ w,   // [CIN, 256]
                       const float* __restrict__ b)   // [256]
{
    constexpr int BM = 64, BK = 16, BN = 256;
    constexpr int KT = (CIN + BK - 1) / BK;
    const float* A = g_agg;   // [N, CIN]
    float* out = g_x;         // [N, 256]

    __shared__ float As[BK][BM];
    __shared__ float Bs[2][BK][BN];

    const int tid = threadIdx.x;
    const int tn  = tid & 31;
    const int ty  = tid >> 5;
    const int n0  = blockIdx.x * BM;

    const uint32_t bs_base =
        (uint32_t)__cvta_generic_to_shared(&Bs[0][0][0]);

    unsigned long long acc2[4][8];
#pragma unroll
    for (int p = 0; p < 4; p++)
#pragma unroll
        for (int j = 0; j < 8; j++) acc2[p][j] = 0ull;

    const int cnA = (tn >> 3) * 64 + (tn & 7) * 4;
    const int lm = tid & 63;
    const int lk = (tid >> 6) * 4;
    const int arow = n0 + lm;

    auto issueB = [&](int kt, int s) {
        const int k0 = kt * BK;
#pragma unroll
        for (int j = 0; j < 4; j++) {
            int ls = tid + j * 256;
            int k = ls >> 6;
            int n = (ls & 63) * 4;
            int kg = k0 + k;
            uint32_t dst = bs_base + (uint32_t)(((s * BK + k) * BN + n) * 4);
            int sz = ((CIN % BK == 0) || kg < CIN) ? 16 : 0;
            const float* src = sz ? &w[kg * BN + n] : w;
            cp16(dst, src, sz);
        }
        cp_commit();
    };
    auto loadA = [&](int kt) -> float4 {
        int kg = kt * BK + lk;
        float4 v = make_float4(0.f, 0.f, 0.f, 0.f);
        if (arow < CONST_N) {
            if (kg + 3 < CIN) {
                v = *(const float4*)&A[(size_t)arow * CIN + kg];
            } else {
                float* o = &v.x;
#pragma unroll
                for (int j = 0; j < 4; j++)
                    o[j] = (kg + j < CIN) ? A[(size_t)arow * CIN + kg + j] : 0.f;
            }
        }
        return v;
    };

    issueB(0, 0);
    float4 apre = loadA(0);

    for (int kt = 0; kt < KT; kt++) {
        const int s = kt & 1;
        __syncthreads();                          // (a)
        if (kt + 1 < KT) issueB(kt + 1, s ^ 1);
        As[lk + 0][lm] = apre.x;
        As[lk + 1][lm] = apre.y;
        As[lk + 2][lm] = apre.z;
        As[lk + 3][lm] = apre.w;
        if (kt + 1 < KT) cp_wait1(); else cp_wait0();
        __syncthreads();                          // (b)
        if (kt + 1 < KT) apre = loadA(kt + 1);    // overlaps compute
#pragma unroll
        for (int k = 0; k < BK; k++) {
            const unsigned long long* a64 =
                (const unsigned long long*)&As[k][ty * 8];
            unsigned long long a2[4] = {a64[0], a64[1], a64[2], a64[3]};
            unsigned long long bb[8];
            float4 bA = *(const float4*)&Bs[s][k][cnA];
            float4 bB = *(const float4*)&Bs[s][k][cnA + 32];
            bb[0] = pack2(bA.x, bA.x);
            bb[1] = pack2(bA.y, bA.y);
            bb[2] = pack2(bA.z, bA.z);
            bb[3] = pack2(bA.w, bA.w);
            bb[4] = pack2(bB.x, bB.x);
            bb[5] = pack2(bB.y, bB.y);
            bb[6] = pack2(bB.z, bB.z);
            bb[7] = pack2(bB.w, bB.w);
#pragma unroll
            for (int p = 0; p < 4; p++)
#pragma unroll
                for (int j = 0; j < 8; j++) ffma2(acc2[p][j], a2[p], bb[j]);
        }
    }

    float4 biasA = *(const float4*)&b[cnA];
    float4 biasB = *(const float4*)&b[cnA + 32];
#pragma unroll
    for (int i = 0; i < 8; i++) {
        int row = n0 + ty * 8 + i;
        if (row >= CONST_N) continue;
        {
            float2 f0 = unpack2(acc2[i >> 1][0]);
            float2 f1 = unpack2(acc2[i >> 1][1]);
            float2 f2 = unpack2(acc2[i >> 1][2]);
            float2 f3 = unpack2(acc2[i >> 1][3]);
            float4 o;
            o.x = softplus_f(((i & 1) ? f0.y : f0.x) + biasA.x);
            o.y = softplus_f(((i & 1) ? f1.y : f1.x) + biasA.y);
            o.z = softplus_f(((i & 1) ? f2.y : f2.x) + biasA.z);
            o.w = softplus_f(((i & 1) ? f3.y : f3.x) + biasA.w);
            *(float4*)&out[(size_t)row * 256 + cnA] = o;
        }
        {
            float2 f4 = unpack2(acc2[i >> 1][4]);
            float2 f5 = unpack2(acc2[i >> 1][5]);
            float2 f6 = unpack2(acc2[i >> 1][6]);
            float2 f7 = unpack2(acc2[i >> 1][7]);
            float4 o;
            o.x = softplus_f(((i & 1) ? f4.y : f4.x) + biasB.x);
            o.y = softplus_f(((i & 1) ? f5.y : f5.x) + biasB.y);
            o.z = softplus_f(((i & 1) ? f6.y : f6.x) + biasB.z);
            o.w = softplus_f(((i & 1) ? f7.y : f7.x) + biasB.w);
            *(float4*)&out[(size_t)row * 256 + cnA + 32] = o;
        }
    }
}

// ---------------- global mean pool (atomics; batch is L2-hot) --------------
__global__ void poolC_kernel(const int* __restrict__ batch) {
    int i = blockIdx.x * blockDim.x + threadIdx.x;
    if (i >= CONST_N * 64) return;
    int n = i >> 6;
    int c4 = i & 63;
    int bg = batch[n];
    float4 v = *(const float4*)&g_x[(size_t)n * 256 + c4 * 4];
    red_add_f4(&g_gsum[bg * 256 + c4 * 4], v);
    if (c4 == 0) atomicAdd(&g_gcnt[bg], 1.f);
}

// ---------------- readout MLP (one block per graph) ------------------------
__global__ __launch_bounds__(256)
void readoutC_kernel(const float* __restrict__ rw1, const float* __restrict__ rb1,
                     const float* __restrict__ rw2, const float* __restrict__ rb2,
                     const float* __restrict__ rw3, const float* __restrict__ rb3,
                     float* __restrict__ out) {
    __shared__ float gs[256];
    __shared__ float h1s[256];
    __shared__ float h2s[128];
    __shared__ float red_s[8];
    int g = blockIdx.x;
    int c = threadIdx.x;
    float cnt = fmaxf(g_gcnt[g], 1.f);
    gs[c] = g_gsum[g * 256 + c] / cnt;
    __syncthreads();
    float z = rb1[c];
#pragma unroll 8
    for (int k = 0; k < 256; k++) z += gs[k] * rw1[k * 256 + c];
    h1s[c] = softplus_f(z);
    __syncthreads();
    if (c < 128) {
        float z2 = rb2[c];
#pragma unroll 8
        for (int k = 0; k < 256; k++) z2 += h1s[k] * rw2[k * 128 + c];
        h2s[c] = softplus_f(z2);
    }
    __syncthreads();
    float p = (c < 128) ? h2s[c] * rw3[c] : 0.f;
#pragma unroll
    for (int off = 16; off; off >>= 1) p += __shfl_down_sync(0xffffffffu, p, off);
    if ((c & 31) == 0) red_s[c >> 5] = p;
    __syncthreads();
    if (c == 0) {
        float t = 0.f;
#pragma unroll
        for (int i = 0; i < 8; i++) t += red_s[i];
        out[g] = t + rb3[0];
    }
}

// ---------------- launch ----------------------------------------------------
extern "C" void kernel_launch(void* const* d_in, const int* in_sizes, int n_in,
                              void* d_out, int out_size) {
    (void)in_sizes; (void)n_in; (void)out_size;
    const int*   x_atoms = (const int*)d_in[0];
    const int*   ei      = (const int*)d_in[1];
    const float* ea      = (const float*)d_in[2];
    const int*   batch   = (const int*)d_in[3];
    const float* emb     = (const float*)d_in[4];
    const float* ew1_0   = (const float*)d_in[5];
    const float* eb1_0   = (const float*)d_in[6];
    const float* ew2_0   = (const float*)d_in[7];
    const float* eb2_0   = (const float*)d_in[8];
    const float* nw_0    = (const float*)d_in[9];
    const float* nb_0    = (const float*)d_in[10];
    const float* ew1     = (const float*)d_in[11];
    const float* eb1     = (const float*)d_in[12];
    const float* ew2     = (const float*)d_in[13];
    const float* eb2     = (const float*)d_in[14];
    const float* nw      = (const float*)d_in[15];
    const float* nb      = (const float*)d_in[16];
    const float* rw1     = (const float*)d_in[17];
    const float* rb1     = (const float*)d_in[18];
    const float* rw2     = (const float*)d_in[19];
    const float* rb2     = (const float*)d_in[20];
    const float* rw3     = (const float*)d_in[21];
    const float* rb3     = (const float*)d_in[22];
    float* out = (float*)d_out;

    const int* srcg = ei;
    const int* dstg = ei + CONST_E;

    const int EB = (CONST_E + 63) / 64;   // 4688
    const int NB = (CONST_N + 63) / 64;   // 391

    embedC_kernel<<<(CONST_N * DIM0 + 255) / 256, 256>>>(x_atoms, emb);

    // layer 0 (92-dim)
    zeroC_agg_kernel<<<1024, 256>>>(CONST_N * DIM0 / 4);
    edgeC_conv_kernel<DIM0, 128><<<EB, 256>>>(ea, srcg, dstg,
                                              ew1_0, eb1_0, ew2_0, eb2_0);
    nodeC_gemm_kernel<DIM0><<<NB, 256>>>(nw_0, nb_0);

    // layers 1..3 (256-dim)
    for (int i = 0; i < 3; i++) {
        zeroC_agg_kernel<<<2048, 256>>>(CONST_N * DIM1 / 4);
        edgeC_conv_kernel<DIM1, 256><<<EB, 256>>>(
            ea, srcg, dstg,
            ew1 + i * 4 * DIM1, eb1 + i * DIM1,
            ew2 + i * DIM1 * DIM1, eb2 + i * DIM1);
        nodeC_gemm_kernel<DIM1><<<NB, 256>>>(nw + i * DIM1 * DIM1, nb + i * DIM1);
    }

    // pooling + readout
    zeroC_pool_kernel<<<(CONST_G * DIM1 + 255) / 256, 256>>>();
    poolC_kernel<<<(CONST_N * 64 + 255) / 256, 256>>>(batch);
    readoutC_kernel<<<CONST_G, 256>>>(rw1, rb1, rw2, rb2, rw3, rb3, out);
}